// round 8
// baseline (speedup 1.0000x reference)
#include <cuda_runtime.h>
#include <cuda_bf16.h>
#include <math.h>
#include <stdint.h>

// ---------------- static config ----------------
#define Bq   4
#define Cq   96
#define SSz  4
#define NHq  3
#define MLPH 384
#define TOKENS (Bq*256*256)

#define SCALEq 0.17677669529663687f
#define EPSq   1e-5f

// ---------------- precomputed bf16 tables ----------------
static __device__ __align__(16) __nv_bfloat16 g_bias[3 * 64 * 64];
static __device__ __align__(16) __nv_bfloat16 g_qkvw[288 * 96];
static __device__ __align__(16) __nv_bfloat16 g_projw[96 * 96];
static __device__ __align__(16) __nv_bfloat16 g_fc1w[384 * 96];
static __device__ __align__(16) __nv_bfloat16 g_fc2w[96 * 384];

// ---------------- warp-mma helpers ----------------
__device__ __forceinline__ uint32_t smem_u32(const void* p) {
    uint32_t a;
    asm("{ .reg .u64 t; cvta.to.shared.u64 t, %1; cvt.u32.u64 %0, t; }" : "=r"(a) : "l"(p));
    return a;
}
__device__ __forceinline__ void ldm4(uint32_t* r, uint32_t addr) {
    asm volatile("ldmatrix.sync.aligned.m8n8.x4.shared.b16 {%0,%1,%2,%3}, [%4];"
        : "=r"(r[0]), "=r"(r[1]), "=r"(r[2]), "=r"(r[3]) : "r"(addr));
}
__device__ __forceinline__ void stm4(uint32_t addr, uint32_t r0, uint32_t r1, uint32_t r2, uint32_t r3) {
    asm volatile("stmatrix.sync.aligned.m8n8.x4.shared.b16 [%0], {%1,%2,%3,%4};"
        :: "r"(addr), "r"(r0), "r"(r1), "r"(r2), "r"(r3));
}
__device__ __forceinline__ void stm4t(uint32_t addr, uint32_t r0, uint32_t r1, uint32_t r2, uint32_t r3) {
    asm volatile("stmatrix.sync.aligned.m8n8.x4.trans.shared.b16 [%0], {%1,%2,%3,%4};"
        :: "r"(addr), "r"(r0), "r"(r1), "r"(r2), "r"(r3));
}
__device__ __forceinline__ void mma_bf16(float* c, const uint32_t* a, const uint32_t* b) {
    asm volatile("mma.sync.aligned.m16n8k16.row.col.f32.bf16.bf16.f32 "
        "{%0,%1,%2,%3}, {%4,%5,%6,%7}, {%8,%9}, {%0,%1,%2,%3};"
        : "+f"(c[0]), "+f"(c[1]), "+f"(c[2]), "+f"(c[3])
        : "r"(a[0]), "r"(a[1]), "r"(a[2]), "r"(a[3]), "r"(b[0]), "r"(b[1]));
}
__device__ __forceinline__ float gelu_f(float v) {
    return 0.5f * v * (1.0f + erff(v * 0.70710678118654752f));
}
__device__ __forceinline__ uint32_t packbf(float a, float b) {
    const __nv_bfloat162 h = __floats2bfloat162_rn(a, b);
    return *(const uint32_t*)&h;
}
__device__ __forceinline__ float2 unpackbf(uint32_t u) {
    const __nv_bfloat162 h = *(const __nv_bfloat162*)&u;
    return make_float2(__bfloat162float(h.x), __bfloat162float(h.y));
}

// ================= prep: bias gather + weight bf16 conversion =================
__global__ void prep_kernel(const float* __restrict__ rpb, const int* __restrict__ rel_index,
                            const float* __restrict__ qkv_w, const float* __restrict__ proj_w,
                            const float* __restrict__ fc1_w, const float* __restrict__ fc2_w)
{
    const int idx = blockIdx.x * 256 + threadIdx.x;   // 144*256 = 36864
    if (idx < 3 * 4096) {
        const int hh = idx >> 12, ij = idx & 4095;
        g_bias[hh * 4096 + ij] = __float2bfloat16(rpb[rel_index[ij] * 3 + hh]);
    }
    if (idx < 288 * 96) g_qkvw[idx] = __float2bfloat16(qkv_w[idx]);
    if (idx < 96 * 96)  g_projw[idx] = __float2bfloat16(proj_w[idx]);
    if (idx < 384 * 96) {
        g_fc1w[idx] = __float2bfloat16(fc1_w[idx]);
        g_fc2w[idx] = __float2bfloat16(fc2_w[idx]);
    }
}

// ---------------- fused smem layout (bytes) ----------------
#define SAT 104     // a_s / k_s / B1 row stride (bf16) -> 208 B
#define SVT 136     // vt_s / B2 / H row stride (bf16)  -> 272 B
#define AS_A  0                      // [128][104] bf16: LN1 -> O -> LN2'd MLP A
#define AS_K  26624                  // [128][104]: K -> MLP B1/B2 staging
#define AS_VT 53248                  // [96][136]: v^T -> MLP H1 [128][136] (extends into AS_W)
#define AS_W  79360                  // [96][104]: weight chunk (qkv/proj)
#define AS_TOTAL 99328

// ================= fused block kernel: 2 windows (128 tokens) per CTA =========
__global__ __launch_bounds__(256, 2)
void swin_block_fused(const float* __restrict__ x,
                      const float* __restrict__ g1, const float* __restrict__ b1,
                      const float* __restrict__ qkv_b, const float* __restrict__ proj_b,
                      const float* __restrict__ g2, const float* __restrict__ b2,
                      const float* __restrict__ fc1_b, const float* __restrict__ fc2_b,
                      const float* __restrict__ attn_mask,
                      float* __restrict__ out)
{
    extern __shared__ __align__(16) char smem[];
    const uint32_t sb = smem_u32(smem);
    const int tid = threadIdx.x, lane = tid & 31, warp = tid >> 5;

    const int wglob = blockIdx.x * 2 + (warp >> 2);
    const int b     = wglob >> 10;
    const int wrem  = wglob & 1023;
    const int wy    = wrem >> 5, wx = wrem & 31;
    const int wl    = warp >> 2;
    const int mrow0 = warp * 16;

    // ---- LN1 + gather -> a_s bf16 [128][104] ----
    #pragma unroll
    for (int r = 0; r < 16; r++) {
        const int t = mrow0 + r;
        const int i = t & 63;
        const int yy = (wy * 8 + (i >> 3) + SSz) & 255;
        const int xx = (wx * 8 + (i & 7) + SSz) & 255;
        const float* row = x + (size_t)(b * 65536 + yy * 256 + xx) * Cq;
        float v0 = row[lane], v1 = row[lane + 32], v2 = row[lane + 64];
        float s  = v0 + v1 + v2;
        float ss = v0 * v0 + v1 * v1 + v2 * v2;
        #pragma unroll
        for (int o = 16; o; o >>= 1) {
            s  += __shfl_xor_sync(0xffffffffu, s,  o);
            ss += __shfl_xor_sync(0xffffffffu, ss, o);
        }
        const float mu  = s * (1.0f / 96.0f);
        const float var = ss * (1.0f / 96.0f) - mu * mu;
        const float inv = rsqrtf(var + EPSq);
        __nv_bfloat16* arow = (__nv_bfloat16*)(smem + AS_A) + t * SAT;
        arow[lane]      = __float2bfloat16((v0 - mu) * inv * g1[lane]      + b1[lane]);
        arow[lane + 32] = __float2bfloat16((v1 - mu) * inv * g1[lane + 32] + b1[lane + 32]);
        arow[lane + 64] = __float2bfloat16((v2 - mu) * inv * g1[lane + 64] + b1[lane + 64]);
    }
    __syncthreads();

    // ---- A fragments (reused across all 3 qkv chunks) ----
    uint32_t afr[6][4];
    #pragma unroll
    for (int k = 0; k < 6; k++)
        ldm4(afr[k], sb + AS_A + (uint32_t)(((mrow0 + (lane & 15)) * SAT + k * 16 + ((lane >> 4) << 3)) * 2));

    const int g = lane >> 2, tq = lane & 3;

    // ---- stmatrix per-lane base addresses ----
    const int st_r = lane & 7, st_sel = lane >> 3;
    const uint32_t st_row  = st_r + ((st_sel & 1) << 3);        // row within 16-row tile
    const uint32_t st_colb = (uint32_t)((st_sel & 2) << 3);     // 0 or 16 bytes (col block)
    const uint32_t stA = sb + AS_A + (mrow0 + st_row) * 208 + st_colb;
    const uint32_t stK = sb + AS_K + (mrow0 + st_row) * 208 + st_colb;
    const uint32_t stH = sb + AS_VT + (mrow0 + st_row) * 272 + st_colb;
    // trans store for V^T: dest row block from (sel&2), dest col block from (sel&1)
    const uint32_t stVT = sb + AS_VT + (st_r + ((st_sel & 2) << 2)) * 272
                        + ((uint32_t)(st_sel & 1) << 4)
                        + (uint32_t)(wl * 64 + (warp & 3) * 16) * 2;

    // ---- QKV (Q->regs, K->smem, V^T->smem) ----
    uint32_t qafr[6][4];
    #pragma unroll
    for (int chunk = 0; chunk < 3; chunk++) {
        for (int idx = tid; idx < 1152; idx += 256) {
            const int row = idx / 12, q = idx % 12;
            *(uint4*)(smem + AS_W + row * 208 + q * 16) =
                *(const uint4*)((const char*)g_qkvw + chunk * 18432 + row * 192 + q * 16);
        }
        __syncthreads();

        #pragma unroll
        for (int nt2 = 0; nt2 < 6; nt2++) {
            float c0[4] = {0.f,0.f,0.f,0.f}, c1[4] = {0.f,0.f,0.f,0.f};
            #pragma unroll
            for (int kt = 0; kt < 6; kt++) {
                uint32_t bfr[4];
                ldm4(bfr, sb + AS_W + (uint32_t)(((nt2 * 16 + (lane & 7) + ((lane & 16) ? 8 : 0)) * SAT
                                                 + kt * 16 + ((lane & 8) ? 8 : 0)) * 2));
                mma_bf16(c0, afr[kt], bfr);
                mma_bf16(c1, afr[kt], bfr + 2);
            }
            const int n = nt2 * 16 + 2 * tq;
            if (chunk == 0) {
                const float b0 = qkv_b[n],     b1v = qkv_b[n + 1];
                const float b8 = qkv_b[n + 8], b9  = qkv_b[n + 9];
                qafr[nt2][0] = packbf((c0[0] + b0) * SCALEq, (c0[1] + b1v) * SCALEq);
                qafr[nt2][1] = packbf((c0[2] + b0) * SCALEq, (c0[3] + b1v) * SCALEq);
                qafr[nt2][2] = packbf((c1[0] + b8) * SCALEq, (c1[1] + b9) * SCALEq);
                qafr[nt2][3] = packbf((c1[2] + b8) * SCALEq, (c1[3] + b9) * SCALEq);
            } else if (chunk == 1) {
                const float b0 = qkv_b[96 + n],     b1v = qkv_b[96 + n + 1];
                const float b8 = qkv_b[96 + n + 8], b9  = qkv_b[96 + n + 9];
                stm4(stK + nt2 * 32,
                     packbf(c0[0] + b0, c0[1] + b1v), packbf(c0[2] + b0, c0[3] + b1v),
                     packbf(c1[0] + b8, c1[1] + b9),  packbf(c1[2] + b8, c1[3] + b9));
            } else {
                const float b0 = qkv_b[192 + n],     b1v = qkv_b[192 + n + 1];
                const float b8 = qkv_b[192 + n + 8], b9  = qkv_b[192 + n + 9];
                stm4t(stVT + (uint32_t)(nt2 * 16) * 272,
                      packbf(c0[0] + b0, c0[1] + b1v), packbf(c0[2] + b0, c0[3] + b1v),
                      packbf(c1[0] + b8, c1[1] + b9),  packbf(c1[2] + b8, c1[3] + b9));
            }
        }
        __syncthreads();
    }

    // ---- mask preload ----
    const int i0 = (warp & 3) * 16;
    uint32_t mreg[16];
    {
        const float* mbase = attn_mask + (size_t)wrem * 4096;
        #pragma unroll
        for (int nt2 = 0; nt2 < 4; nt2++)
            #pragma unroll
            for (int t2 = 0; t2 < 2; t2++) {
                const int col = nt2 * 16 + t2 * 8 + 2 * tq;
                const int id = (nt2 * 2 + t2) * 2;
                mreg[id]     = packbf(mbase[(i0 + g) * 64 + col],     mbase[(i0 + g) * 64 + col + 1]);
                mreg[id + 1] = packbf(mbase[(i0 + g + 8) * 64 + col], mbase[(i0 + g + 8) * 64 + col + 1]);
            }
    }

    // ---- per-head attention ----
    for (int hh = 0; hh < NHq; hh++) {
        float sc[4][8];
        #pragma unroll
        for (int nt2 = 0; nt2 < 4; nt2++) {
            #pragma unroll
            for (int q = 0; q < 8; q++) sc[nt2][q] = 0.f;
            #pragma unroll
            for (int kt2 = 0; kt2 < 2; kt2++) {
                uint32_t bfr[4];
                ldm4(bfr, sb + AS_K + (uint32_t)(((wl * 64 + nt2 * 16 + (lane & 7) + ((lane & 16) ? 8 : 0)) * SAT
                                                 + hh * 32 + kt2 * 16 + ((lane & 8) ? 8 : 0)) * 2));
                mma_bf16(sc[nt2],     qafr[2 * hh + kt2], bfr);
                mma_bf16(sc[nt2] + 4, qafr[2 * hh + kt2], bfr + 2);
            }
        }
        const __nv_bfloat16* bias_h = g_bias + hh * 4096;
        #pragma unroll
        for (int nt2 = 0; nt2 < 4; nt2++)
            #pragma unroll
            for (int t2 = 0; t2 < 2; t2++) {
                const int col = nt2 * 16 + t2 * 8 + 2 * tq;
                #pragma unroll
                for (int rs = 0; rs < 2; rs++) {
                    float* cp = &sc[nt2][t2 * 4 + rs * 2];
                    const float2 bv = unpackbf(*(const uint32_t*)(bias_h + (i0 + g + rs * 8) * 64 + col));
                    const float2 mv = unpackbf(mreg[(nt2 * 2 + t2) * 2 + rs]);
                    cp[0] += bv.x + mv.x;
                    cp[1] += bv.y + mv.y;
                }
            }
        float mx0 = -1e30f, mx1 = -1e30f;
        #pragma unroll
        for (int nt2 = 0; nt2 < 4; nt2++)
            #pragma unroll
            for (int t2 = 0; t2 < 2; t2++) {
                mx0 = fmaxf(mx0, fmaxf(sc[nt2][t2 * 4],     sc[nt2][t2 * 4 + 1]));
                mx1 = fmaxf(mx1, fmaxf(sc[nt2][t2 * 4 + 2], sc[nt2][t2 * 4 + 3]));
            }
        mx0 = fmaxf(mx0, __shfl_xor_sync(0xffffffffu, mx0, 1));
        mx0 = fmaxf(mx0, __shfl_xor_sync(0xffffffffu, mx0, 2));
        mx1 = fmaxf(mx1, __shfl_xor_sync(0xffffffffu, mx1, 1));
        mx1 = fmaxf(mx1, __shfl_xor_sync(0xffffffffu, mx1, 2));
        float s0 = 0.f, s1 = 0.f;
        #pragma unroll
        for (int nt2 = 0; nt2 < 4; nt2++)
            #pragma unroll
            for (int t2 = 0; t2 < 2; t2++) {
                float* cp = &sc[nt2][t2 * 4];
                cp[0] = __expf(cp[0] - mx0); cp[1] = __expf(cp[1] - mx0);
                cp[2] = __expf(cp[2] - mx1); cp[3] = __expf(cp[3] - mx1);
                s0 += cp[0] + cp[1];
                s1 += cp[2] + cp[3];
            }
        s0 += __shfl_xor_sync(0xffffffffu, s0, 1);
        s0 += __shfl_xor_sync(0xffffffffu, s0, 2);
        s1 += __shfl_xor_sync(0xffffffffu, s1, 1);
        s1 += __shfl_xor_sync(0xffffffffu, s1, 2);
        const float inv0 = 1.0f / s0, inv1 = 1.0f / s1;
        uint32_t pa[4][4];
        #pragma unroll
        for (int kt = 0; kt < 4; kt++) {
            pa[kt][0] = packbf(sc[kt][0] * inv0, sc[kt][1] * inv0);
            pa[kt][1] = packbf(sc[kt][2] * inv1, sc[kt][3] * inv1);
            pa[kt][2] = packbf(sc[kt][4] * inv0, sc[kt][5] * inv0);
            pa[kt][3] = packbf(sc[kt][6] * inv1, sc[kt][7] * inv1);
        }
        #pragma unroll
        for (int nb = 0; nb < 2; nb++) {
            float oc0[4] = {0.f,0.f,0.f,0.f}, oc1[4] = {0.f,0.f,0.f,0.f};
            #pragma unroll
            for (int kt = 0; kt < 4; kt++) {
                uint32_t bfr[4];
                ldm4(bfr, sb + AS_VT + (uint32_t)(((hh * 32 + nb * 16 + (lane & 7) + ((lane & 16) ? 8 : 0)) * SVT
                                                  + wl * 64 + kt * 16 + ((lane & 8) ? 8 : 0)) * 2));
                mma_bf16(oc0, pa[kt], bfr);
                mma_bf16(oc1, pa[kt], bfr + 2);
            }
            stm4(stA + (uint32_t)(hh * 32 + nb * 16) * 2,
                 packbf(oc0[0], oc0[1]), packbf(oc0[2], oc0[3]),
                 packbf(oc1[0], oc1[1]), packbf(oc1[2], oc1[3]));
        }
    }
    __syncthreads();

    // ---- stage proj_w -> AS_W and fc1_w chunk0 -> AS_K ----
    for (int idx = tid; idx < 1152; idx += 256) {
        const int row = idx / 12, q = idx % 12;
        *(uint4*)(smem + AS_W + row * 208 + q * 16) =
            *(const uint4*)((const char*)g_projw + row * 192 + q * 16);
    }
    for (int idx = tid; idx < 1536; idx += 256) {
        const int row = idx / 12, q = idx % 12;
        *(uint4*)(smem + AS_K + row * 208 + q * 16) =
            *(const uint4*)((const char*)g_fc1w + row * 192 + q * 16);
    }
    __syncthreads();

    // ---- residual base addresses ----
    size_t baseA, baseB;
    {
        const int tA = mrow0 + g, tB = tA + 8;
        const int iA = tA & 63, iB = tB & 63;
        const int yyA = (wy * 8 + (iA >> 3) + SSz) & 255, xxA = (wx * 8 + (iA & 7) + SSz) & 255;
        const int yyB = (wy * 8 + (iB >> 3) + SSz) & 255, xxB = (wx * 8 + (iB & 7) + SSz) & 255;
        baseA = ((size_t)(b * 65536 + yyA * 256 + xxA)) * Cq;
        baseB = ((size_t)(b * 65536 + yyB * 256 + xxB)) * Cq;
    }

    // ---- proj mma: x2 stays in registers ----
    float x2v[6][2][4];
    {
        uint32_t ofr2[6][4];
        #pragma unroll
        for (int k = 0; k < 6; k++)
            ldm4(ofr2[k], sb + AS_A + (uint32_t)(((mrow0 + (lane & 15)) * SAT + k * 16 + ((lane >> 4) << 3)) * 2));

        #pragma unroll
        for (int nt2 = 0; nt2 < 6; nt2++) {
            float c0[4] = {0.f,0.f,0.f,0.f}, c1[4] = {0.f,0.f,0.f,0.f};
            #pragma unroll
            for (int kt = 0; kt < 6; kt++) {
                uint32_t bfr[4];
                ldm4(bfr, sb + AS_W + (uint32_t)(((nt2 * 16 + (lane & 7) + ((lane & 16) ? 8 : 0)) * SAT
                                                 + kt * 16 + ((lane & 8) ? 8 : 0)) * 2));
                mma_bf16(c0, ofr2[kt], bfr);
                mma_bf16(c1, ofr2[kt], bfr + 2);
            }
            const int n = nt2 * 16 + 2 * tq;
            {
                const float b0 = proj_b[n], b1v = proj_b[n + 1];
                const float2 xA = *(const float2*)(x + baseA + n);
                const float2 xB = *(const float2*)(x + baseB + n);
                x2v[nt2][0][0] = xA.x + c0[0] + b0;  x2v[nt2][0][1] = xA.y + c0[1] + b1v;
                x2v[nt2][0][2] = xB.x + c0[2] + b0;  x2v[nt2][0][3] = xB.y + c0[3] + b1v;
            }
            {
                const float b0 = proj_b[n + 8], b1v = proj_b[n + 9];
                const float2 xA = *(const float2*)(x + baseA + n + 8);
                const float2 xB = *(const float2*)(x + baseB + n + 8);
                x2v[nt2][1][0] = xA.x + c1[0] + b0;  x2v[nt2][1][1] = xA.y + c1[1] + b1v;
                x2v[nt2][1][2] = xB.x + c1[2] + b0;  x2v[nt2][1][3] = xB.y + c1[3] + b1v;
            }
        }
    }

    // ---- LN2 in registers (quad reductions) -> A bf16 (stmatrix) ----
    {
        float s0 = 0.f, ss0 = 0.f, s1 = 0.f, ss1 = 0.f;
        #pragma unroll
        for (int nt2 = 0; nt2 < 6; nt2++)
            #pragma unroll
            for (int tl = 0; tl < 2; tl++) {
                const float a0 = x2v[nt2][tl][0], a1 = x2v[nt2][tl][1];
                const float a2 = x2v[nt2][tl][2], a3 = x2v[nt2][tl][3];
                s0 += a0 + a1;  ss0 += a0 * a0 + a1 * a1;
                s1 += a2 + a3;  ss1 += a2 * a2 + a3 * a3;
            }
        s0  += __shfl_xor_sync(0xffffffffu, s0, 1);  s0  += __shfl_xor_sync(0xffffffffu, s0, 2);
        ss0 += __shfl_xor_sync(0xffffffffu, ss0, 1); ss0 += __shfl_xor_sync(0xffffffffu, ss0, 2);
        s1  += __shfl_xor_sync(0xffffffffu, s1, 1);  s1  += __shfl_xor_sync(0xffffffffu, s1, 2);
        ss1 += __shfl_xor_sync(0xffffffffu, ss1, 1); ss1 += __shfl_xor_sync(0xffffffffu, ss1, 2);
        const float mu0 = s0 * (1.0f / 96.0f);
        const float iv0 = rsqrtf(ss0 * (1.0f / 96.0f) - mu0 * mu0 + EPSq);
        const float mu1 = s1 * (1.0f / 96.0f);
        const float iv1 = rsqrtf(ss1 * (1.0f / 96.0f) - mu1 * mu1 + EPSq);
        #pragma unroll
        for (int nt2 = 0; nt2 < 6; nt2++) {
            const int n = nt2 * 16 + 2 * tq;
            const float ga0 = g2[n], gb0 = g2[n + 1], ba0 = b2[n], bb0 = b2[n + 1];
            const float ga1 = g2[n + 8], gb1 = g2[n + 9], ba1 = b2[n + 8], bb1 = b2[n + 9];
            stm4(stA + nt2 * 32,
                 packbf((x2v[nt2][0][0] - mu0) * iv0 * ga0 + ba0,
                        (x2v[nt2][0][1] - mu0) * iv0 * gb0 + bb0),
                 packbf((x2v[nt2][0][2] - mu1) * iv1 * ga0 + ba0,
                        (x2v[nt2][0][3] - mu1) * iv1 * gb0 + bb0),
                 packbf((x2v[nt2][1][0] - mu0) * iv0 * ga1 + ba1,
                        (x2v[nt2][1][1] - mu0) * iv0 * gb1 + bb1),
                 packbf((x2v[nt2][1][2] - mu1) * iv1 * ga1 + ba1,
                        (x2v[nt2][1][3] - mu1) * iv1 * gb1 + bb1));
        }
    }
    __syncthreads();   // proj_w dead; B1 chunk0 visible; H region free

    // ---- MLP ----
    uint32_t mafr[6][4];
    #pragma unroll
    for (int k = 0; k < 6; k++)
        ldm4(mafr[k], sb + AS_A + (uint32_t)(((mrow0 + (lane & 15)) * SAT + k * 16 + ((lane >> 4) << 3)) * 2));

    float ofr[6][2][4];
    #pragma unroll
    for (int i = 0; i < 6; i++)
        #pragma unroll
        for (int j = 0; j < 2; j++)
            #pragma unroll
            for (int q = 0; q < 4; q++) ofr[i][j][q] = 0.f;

    for (int chunk = 0; chunk < 3; chunk++) {
        if (chunk > 0) {
            __syncthreads();
            for (int idx = tid; idx < 1536; idx += 256) {
                const int row = idx / 12, q = idx % 12;
                *(uint4*)(smem + AS_K + row * 208 + q * 16) =
                    *(const uint4*)((const char*)g_fc1w + chunk * 24576 + row * 192 + q * 16);
            }
            __syncthreads();
        }

        // FC1 + GELU -> H (stmatrix)
        #pragma unroll
        for (int nt2 = 0; nt2 < 8; nt2++) {
            const int n0 = nt2 * 16;
            float c0[4] = {0.f,0.f,0.f,0.f}, c1[4] = {0.f,0.f,0.f,0.f};
            #pragma unroll
            for (int k = 0; k < 6; k++) {
                uint32_t bfr[4];
                ldm4(bfr, sb + AS_K + (uint32_t)(((n0 + (lane & 7) + ((lane & 16) ? 8 : 0)) * SAT
                                                 + k * 16 + ((lane & 8) ? 8 : 0)) * 2));
                mma_bf16(c0, mafr[k], bfr);
                mma_bf16(c1, mafr[k], bfr + 2);
            }
            const int nn = chunk * 128 + n0 + 2 * tq;
            const float bb0 = fc1_b[nn],     bb1 = fc1_b[nn + 1];
            const float bb8 = fc1_b[nn + 8], bb9 = fc1_b[nn + 9];
            stm4(stH + nt2 * 32,
                 packbf(gelu_f(c0[0] + bb0), gelu_f(c0[1] + bb1)),
                 packbf(gelu_f(c0[2] + bb0), gelu_f(c0[3] + bb1)),
                 packbf(gelu_f(c1[0] + bb8), gelu_f(c1[1] + bb9)),
                 packbf(gelu_f(c1[2] + bb8), gelu_f(c1[3] + bb9)));
        }
        __syncthreads();   // all warps done with B1

        // stage B2 chunk
        for (int idx = tid; idx < 1536; idx += 256) {
            const int row = idx / 16, q = idx % 16;
            *(uint4*)(smem + AS_K + row * 272 + q * 16) =
                *(const uint4*)((const char*)g_fc2w + row * 768 + chunk * 256 + q * 16);
        }
        __syncthreads();

        // FC2 accumulate
        #pragma unroll
        for (int k = 0; k < 8; k++) {
            uint32_t hfr[4];
            ldm4(hfr, sb + AS_VT + (uint32_t)(((mrow0 + (lane & 15)) * SVT + k * 16 + ((lane >> 4) << 3)) * 2));
            #pragma unroll
            for (int nt2 = 0; nt2 < 6; nt2++) {
                uint32_t bfr[4];
                ldm4(bfr, sb + AS_K + (uint32_t)(((nt2 * 16 + (lane & 7) + ((lane & 16) ? 8 : 0)) * SVT
                                                 + k * 16 + ((lane & 8) ? 8 : 0)) * 2));
                mma_bf16(ofr[nt2][0], hfr, bfr);
                mma_bf16(ofr[nt2][1], hfr, bfr + 2);
            }
        }
    }

    // ---- epilogue: out = x2 + mlp + fc2_b (scattered) ----
    #pragma unroll
    for (int nt2 = 0; nt2 < 6; nt2++) {
        #pragma unroll
        for (int tl = 0; tl < 2; tl++) {
            const int n = nt2 * 16 + tl * 8 + 2 * tq;
            const float b0 = fc2_b[n], b1v = fc2_b[n + 1];
            const float* c = ofr[nt2][tl];
            *(float2*)(out + baseA + n) = make_float2(x2v[nt2][tl][0] + c[0] + b0,
                                                      x2v[nt2][tl][1] + c[1] + b1v);
            *(float2*)(out + baseB + n) = make_float2(x2v[nt2][tl][2] + c[2] + b0,
                                                      x2v[nt2][tl][3] + c[3] + b1v);
        }
    }
}

// ================= launch =================
extern "C" void kernel_launch(void* const* d_in, const int* in_sizes, int n_in,
                              void* d_out, int out_size)
{
    const float* x        = (const float*)d_in[0];
    const float* g1       = (const float*)d_in[1];
    const float* b1       = (const float*)d_in[2];
    const float* qkv_w    = (const float*)d_in[3];
    const float* qkv_b    = (const float*)d_in[4];
    const float* rpb      = (const float*)d_in[5];
    const float* proj_w   = (const float*)d_in[6];
    const float* proj_b   = (const float*)d_in[7];
    const float* g2       = (const float*)d_in[8];
    const float* b2       = (const float*)d_in[9];
    const float* fc1_w    = (const float*)d_in[10];
    const float* fc1_b    = (const float*)d_in[11];
    const float* fc2_w    = (const float*)d_in[12];
    const float* fc2_b    = (const float*)d_in[13];
    const float* attn_mask= (const float*)d_in[14];
    const int*   rel_index= (const int*)  d_in[15];
    float* out = (float*)d_out;

    cudaFuncSetAttribute(swin_block_fused, cudaFuncAttributeMaxDynamicSharedMemorySize, AS_TOTAL);

    prep_kernel<<<144, 256>>>(rpb, rel_index, qkv_w, proj_w, fc1_w, fc2_w);
    swin_block_fused<<<TOKENS / 128, 256, AS_TOTAL>>>(x, g1, b1, qkv_b, proj_b,
                                                      g2, b2, fc1_b, fc2_b,
                                                      attn_mask, out);
}